// round 11
// baseline (speedup 1.0000x reference)
#include <cuda_runtime.h>
#include <math.h>
#include <stdint.h>

#define S_LEN 2048
#define B_SZ  64
#define XDIM  64
#define HDIM  256
#define ODIM  64

// Scratch (alloc-free rule: __device__ globals)
__device__ float g_U[S_LEN * B_SZ * HDIM];   // U[t,b,:] = feat @ Wih^T + bih + bhh
__device__ float g_Hs[S_LEN * B_SZ * HDIM];  // hidden state ENTERING step t (h_0 = 0)

// ------------------------- packed fp32x2 helpers ---------------------------
__device__ __forceinline__ unsigned long long fma2(unsigned long long a,
                                                   unsigned long long b,
                                                   unsigned long long c) {
    unsigned long long d;
    asm("fma.rn.f32x2 %0, %1, %2, %3;" : "=l"(d) : "l"(a), "l"(b), "l"(c));
    return d;
}
__device__ __forceinline__ unsigned long long add2(unsigned long long a,
                                                   unsigned long long b) {
    unsigned long long d;
    asm("add.rn.f32x2 %0, %1, %2;" : "=l"(d) : "l"(a), "l"(b));
    return d;
}
__device__ __forceinline__ float pk_lo(unsigned long long v) {
    return __uint_as_float((unsigned)(v & 0xffffffffull));
}
__device__ __forceinline__ float pk_hi(unsigned long long v) {
    return __uint_as_float((unsigned)(v >> 32));
}
// splat one fp32 into both lanes of a packed f32x2
__device__ __forceinline__ unsigned long long pk2(float v) {
    unsigned long long d;
    unsigned u = __float_as_uint(v);
    asm("mov.b64 %0, {%1, %2};" : "=l"(d) : "r"(u), "r"(u));
    return d;
}

__device__ __forceinline__ uint32_t smem_u32(const void* p) {
    uint32_t a;
    asm("{ .reg .u64 t; cvta.to.shared.u64 t, %1; cvt.u32.u64 %0, t; }"
        : "=r"(a) : "l"(p));
    return a;
}
__device__ __forceinline__ uint32_t ctarank() {
    uint32_t r;
    asm("mov.u32 %0, %%cluster_ctarank;" : "=r"(r));
    return r;
}
// remote async store with mbarrier transaction completion (no fence needed)
__device__ __forceinline__ void st_async_peer_f32(uint32_t daddr, uint32_t mbaddr,
                                                  uint32_t peer, float v) {
    asm volatile(
        "{\n\t.reg .b32 ra, rb;\n\t"
        "mapa.shared::cluster.u32 ra, %0, %2;\n\t"
        "mapa.shared::cluster.u32 rb, %1, %2;\n\t"
        "st.async.shared::cluster.mbarrier::complete_tx::bytes.f32 [ra], %3, [rb];\n\t}"
        :: "r"(daddr), "r"(mbaddr), "r"(peer), "f"(v) : "memory");
}
__device__ __forceinline__ void mbar_init(uint32_t addr, uint32_t cnt) {
    asm volatile("mbarrier.init.shared.b64 [%0], %1;" :: "r"(addr), "r"(cnt) : "memory");
}
__device__ __forceinline__ void mbar_expect_tx(uint32_t addr, uint32_t bytes) {
    asm volatile("mbarrier.arrive.expect_tx.shared.b64 _, [%0], %1;"
                 :: "r"(addr), "r"(bytes) : "memory");
}
__device__ __forceinline__ void mbar_wait_cta(uint32_t addr, uint32_t parity) {
    asm volatile(
        "{\n\t.reg .pred P;\n\t"
        "W_%=:\n\t"
        "mbarrier.try_wait.parity.acquire.cta.shared::cta.b64 P, [%0], %1, 0x989680;\n\t"
        "@!P bra W_%=;\n\t}"
        :: "r"(addr), "r"(parity) : "memory");
}

// ---------------------------------------------------------------------------
// Kernel A v2 (R10): feat = tanh(x @ Wx + bx); U = feat @ Wih^T + (bih + bhh)
// ---------------------------------------------------------------------------
__global__ __launch_bounds__(256, 1) void kA(
    const float* __restrict__ x,
    const float* __restrict__ Wx, const float* __restrict__ bx,
    const float* __restrict__ Wih, const float* __restrict__ bih,
    const float* __restrict__ bhh)
{
    extern __shared__ float sm[];
    float* sWx   = sm;                    // [64][128]
    float* sWihT = sWx + 64 * 128;        // [128][260]
    float* sbx   = sWihT + 128 * 260;     // [128]
    float* sbU   = sbx + 128;             // [256]
    float* sx    = sbU + 256;             // [32][64]
    float* sfeat = sx + 32 * 64;          // [32][128]

    const int t = threadIdx.x;

    for (int idx = t; idx < 64 * 128; idx += 256) sWx[idx] = Wx[idx];
    for (int idx = t; idx < 256 * 128; idx += 256) {
        int i = idx >> 7, j = idx & 127;
        sWihT[j * 260 + i] = Wih[idx];
    }
    if (t < 128) sbx[t] = bx[t];
    sbU[t] = bih[t] + bhh[t];
    __syncthreads();

    const int rg = t >> 6;          // 0..3 -> rows rg*8 + q
    const int c2 = t & 63;          // phase1 col pair {2c2, 2c2+1}
    const int ii = c2 * 4;          // phase2: 4 consecutive outputs
    const int ntiles = (S_LEN * B_SZ) / 32;

    for (int tile = blockIdx.x; tile < ntiles; tile += gridDim.x) {
        const int row0 = tile * 32;
        { // load 32x64 x tile (contiguous 8KB = 512 float4)
            const float4* src = (const float4*)(x + (size_t)row0 * XDIM);
            ((float4*)sx)[t]       = src[t];
            ((float4*)sx)[t + 256] = src[t + 256];
        }
        __syncthreads();

        // phase 1: feat = tanh(x @ Wx + bx)   (packed f32x2, 8 rows/thread)
        unsigned long long a[8];
        #pragma unroll
        for (int q = 0; q < 8; q++) a[q] = 0ull;
        #pragma unroll 2
        for (int k4 = 0; k4 < 64; k4 += 4) {
            float xv[8][4];
            #pragma unroll
            for (int q = 0; q < 8; q++)
                *(float4*)&xv[q][0] = *(const float4*)&sx[(rg * 8 + q) * 64 + k4];
            #pragma unroll
            for (int s = 0; s < 4; s++) {
                unsigned long long w =
                    *(const unsigned long long*)&sWx[(k4 + s) * 128 + 2 * c2];
                #pragma unroll
                for (int q = 0; q < 8; q++)
                    a[q] = fma2(pk2(xv[q][s]), w, a[q]);
            }
        }
        {
            const float bx0 = sbx[2 * c2], bx1 = sbx[2 * c2 + 1];
            #pragma unroll
            for (int q = 0; q < 8; q++) {
                const int row = rg * 8 + q;
                sfeat[row * 128 + 2 * c2]     = tanhf(pk_lo(a[q]) + bx0);
                sfeat[row * 128 + 2 * c2 + 1] = tanhf(pk_hi(a[q]) + bx1);
            }
        }
        __syncthreads();

        // phase 2: U = feat @ Wih^T + bias   (packed f32x2, 8 rows/thread)
        unsigned long long acc01[8], acc23[8];
        #pragma unroll
        for (int q = 0; q < 8; q++) { acc01[q] = 0ull; acc23[q] = 0ull; }
        #pragma unroll 2
        for (int j4 = 0; j4 < 128; j4 += 4) {
            float f[8][4];
            #pragma unroll
            for (int q = 0; q < 8; q++)
                *(float4*)&f[q][0] = *(const float4*)&sfeat[(rg * 8 + q) * 128 + j4];
            #pragma unroll
            for (int s = 0; s < 4; s++) {
                ulonglong2 w = *(const ulonglong2*)&sWihT[(j4 + s) * 260 + ii];
                #pragma unroll
                for (int q = 0; q < 8; q++) {
                    unsigned long long fs = pk2(f[q][s]);
                    acc01[q] = fma2(fs, w.x, acc01[q]);
                    acc23[q] = fma2(fs, w.y, acc23[q]);
                }
            }
        }
        float4 bU = *(const float4*)&sbU[ii];
        #pragma unroll
        for (int q = 0; q < 8; q++) {
            float4 o;
            o.x = pk_lo(acc01[q]) + bU.x; o.y = pk_hi(acc01[q]) + bU.y;
            o.z = pk_lo(acc23[q]) + bU.z; o.w = pk_hi(acc23[q]) + bU.w;
            *((float4*)&g_U[(size_t)(row0 + rg * 8 + q) * HDIM + ii]) = o;
        }
        __syncthreads();
    }
}

// ---------------------------------------------------------------------------
// Kernel B v10: R4 skeleton, but TWO batches per 2-CTA cluster, skewed.
// Cluster c owns batches 2c and 2c+1; same Whh registers serve both (weights
// are batch-invariant). Each iteration runs batch-0's full phase (wait ->
// dot -> sync -> finalize+send) then batch-1's. Batch-b's wait at iter t is
// separated from the peer's batch-b send (iter t-1) by the OTHER batch's
// entire phase (~450+ cyc) -> DSMEM flight + mbar wakeup fully hidden; each
// wait should hit the fast path. Per-batch math identical to R4 v4.
// ---------------------------------------------------------------------------
__global__ __launch_bounds__(256, 1) __cluster_dims__(2, 1, 1)
void kB(const float* __restrict__ Whh, const float* __restrict__ sigmas)
{
    __shared__ __align__(16) float sh[2][2][256];   // [batch][buf][idx]
    __shared__ __align__(16) float spart[2][128];   // [batch][i_loc]
    __shared__ __align__(8)  unsigned long long mbar[2][2];  // [batch][parity]

    const int tid   = threadIdx.x;
    const int i_loc = tid & 127;
    const int half  = tid >> 7;
    const uint32_t rank = ctarank();
    const uint32_t peer = rank ^ 1u;
    const int r  = (int)rank;
    const int c  = blockIdx.x >> 1;          // cluster index 0..31
    const int b0 = 2 * c, b1 = 2 * c + 1;    // the two batches we own
    const int gi = r * 128 + i_loc;          // output index this thread serves
    const bool fresh     = (half == r);      // my K-half is produced locally
    const bool finalizer = (half == 0);
    const int waiter_leader = (r == 0) ? 128 : 0;   // one mbar-waiting thread

    // weights: W[gi][128*half + kk], kk in [0,128) -> 32 ulonglong2 = 128 regs
    ulonglong2 wreg[32];
    {
        const ulonglong2* ws =
            (const ulonglong2*)(Whh + (size_t)gi * HDIM + 128 * half);
        #pragma unroll
        for (int i = 0; i < 32; i++) wreg[i] = ws[i];
    }

    const float alpha = 1.0f / (1.0f + expf(-sigmas[gi & 3]));
    const float oma   = 1.0f - alpha;

    // zero both batches' double-buffered h
    #pragma unroll
    for (int q = 0; q < 4; q++) ((float*)sh)[q * 256 + tid] = 0.f;
    const uint32_t mb[2][2] = {
        { smem_u32(&mbar[0][0]), smem_u32(&mbar[0][1]) },
        { smem_u32(&mbar[1][0]), smem_u32(&mbar[1][1]) } };
    const uint32_t sh_a = smem_u32(&sh[0][0][0]);
    if (tid == 0) {
        mbar_init(mb[0][0], 1); mbar_init(mb[0][1], 1);
        mbar_init(mb[1][0], 1); mbar_init(mb[1][1], 1);
    }
    __syncthreads();
    if (tid == waiter_leader) {              // cover sends of steps 0 and 1
        mbar_expect_tx(mb[0][0], 512); mbar_expect_tx(mb[0][1], 512);
        mbar_expect_tx(mb[1][0], 512); mbar_expect_tx(mb[1][1], 512);
    }
    __syncthreads();
    asm volatile("barrier.cluster.arrive.aligned;" ::: "memory");
    asm volatile("barrier.cluster.wait.aligned;" ::: "memory");

    float h0 = 0.f, h1 = 0.f;                // finalizer-owned h[gi] per batch
    float u0n = finalizer ? g_U[(size_t)b0 * HDIM + gi] : 0.f;
    float u1n = finalizer ? g_U[(size_t)b1 * HDIM + gi] : 0.f;

    for (int t = 0; t < S_LEN; t++) {
        const int rb = (t + 1) & 1;          // read buffer for step t
        const int wb = t & 1;                // write buffer for step t
        const uint32_t wpar = (uint32_t)(((t - 1) >> 1) & 1);
        const int pm = (t - 1) & 1;

        // ================= batch 0 phase =================
        {
            const float* hsrc = sh[0][rb] + 128 * half;
            if (!fresh && t > 0) {
                mbar_wait_cta(mb[0][pm], wpar);
                if (tid == waiter_leader) mbar_expect_tx(mb[0][pm], 512);
            }
            unsigned long long a0 = 0ull, a1 = 0ull, a2 = 0ull, a3 = 0ull;
            #pragma unroll
            for (int i = 0; i < 32; i += 2) {
                ulonglong2 hv0 = *(const ulonglong2*)&hsrc[i * 4];
                a0 = fma2(wreg[i].x, hv0.x, a0);
                a1 = fma2(wreg[i].y, hv0.y, a1);
                ulonglong2 hv1 = *(const ulonglong2*)&hsrc[i * 4 + 4];
                a2 = fma2(wreg[i + 1].x, hv1.x, a2);
                a3 = fma2(wreg[i + 1].y, hv1.y, a3);
            }
            unsigned long long cc = add2(add2(a0, a1), add2(a2, a3));
            const float partial = pk_lo(cc) + pk_hi(cc);

            if (!finalizer) spart[0][i_loc] = partial;
            __syncthreads();

            if (finalizer) {
                const float u = u0n;
                if (t + 1 < S_LEN)
                    u0n = g_U[((size_t)(t + 1) * B_SZ + b0) * HDIM + gi];
                g_Hs[((size_t)t * B_SZ + b0) * HDIM + gi] = h0;

                const float s  = partial + spart[0][i_loc] + u;
                h0 = oma * h0 + alpha * tanhf(s);

                sh[0][wb][gi] = h0;                          // local publish
                st_async_peer_f32(sh_a + (uint32_t)(((0 * 2 + wb) * 256 + gi) * 4),
                                  mb[0][wb], peer, h0);      // remote + tx
            }
            __syncthreads();
        }

        // ================= batch 1 phase =================
        {
            const float* hsrc = sh[1][rb] + 128 * half;
            if (!fresh && t > 0) {
                mbar_wait_cta(mb[1][pm], wpar);
                if (tid == waiter_leader) mbar_expect_tx(mb[1][pm], 512);
            }
            unsigned long long a0 = 0ull, a1 = 0ull, a2 = 0ull, a3 = 0ull;
            #pragma unroll
            for (int i = 0; i < 32; i += 2) {
                ulonglong2 hv0 = *(const ulonglong2*)&hsrc[i * 4];
                a0 = fma2(wreg[i].x, hv0.x, a0);
                a1 = fma2(wreg[i].y, hv0.y, a1);
                ulonglong2 hv1 = *(const ulonglong2*)&hsrc[i * 4 + 4];
                a2 = fma2(wreg[i + 1].x, hv1.x, a2);
                a3 = fma2(wreg[i + 1].y, hv1.y, a3);
            }
            unsigned long long cc = add2(add2(a0, a1), add2(a2, a3));
            const float partial = pk_lo(cc) + pk_hi(cc);

            if (!finalizer) spart[1][i_loc] = partial;
            __syncthreads();

            if (finalizer) {
                const float u = u1n;
                if (t + 1 < S_LEN)
                    u1n = g_U[((size_t)(t + 1) * B_SZ + b1) * HDIM + gi];
                g_Hs[((size_t)t * B_SZ + b1) * HDIM + gi] = h1;

                const float s  = partial + spart[1][i_loc] + u;
                h1 = oma * h1 + alpha * tanhf(s);

                sh[1][wb][gi] = h1;                          // local publish
                st_async_peer_f32(sh_a + (uint32_t)(((1 * 2 + wb) * 256 + gi) * 4),
                                  mb[1][wb], peer, h1);      // remote + tx
            }
            __syncthreads();
        }
    }

    asm volatile("barrier.cluster.arrive.aligned;" ::: "memory");
    asm volatile("barrier.cluster.wait.aligned;" ::: "memory");
}

// ---------------------------------------------------------------------------
// Kernel C v2 (R10): z = tanh(h @ Whx + bhx); y = z @ Wout + bout
// ---------------------------------------------------------------------------
__global__ __launch_bounds__(256, 1) void kC(
    const float* __restrict__ Whx, const float* __restrict__ bhx,
    const float* __restrict__ Wout, const float* __restrict__ bout,
    float* __restrict__ y)
{
    extern __shared__ float sm[];
    float* sWhx  = sm;                   // [256][128]
    float* sWout = sWhx + 256 * 128;     // [128][64]
    float* sbhx  = sWout + 128 * 64;     // [128]
    float* sbout = sbhx + 128;           // [64]
    float* sht   = sbout + 64;           // [32][256]
    float* sz    = sht + 32 * 256;       // [32][128]

    const int t = threadIdx.x;
    for (int idx = t; idx < 256 * 128; idx += 256) sWhx[idx] = Whx[idx];
    for (int idx = t; idx < 128 * 64; idx += 256) sWout[idx] = Wout[idx];
    if (t < 128) sbhx[t] = bhx[t];
    if (t < 64)  sbout[t] = bout[t];
    __syncthreads();

    const int rg  = t >> 5;          // 0..7 -> rows rg*4 + q   (phase1)
    const int jj4 = (t & 31) * 4;    // phase1: 4 consecutive z cols
    const int rr  = t >> 4;          // 0..15 -> rows rr*2 + q2 (phase2)
    const int oo4 = (t & 15) * 4;    // phase2: 4 consecutive outputs
    const int ntiles = (S_LEN * B_SZ) / 32;

    for (int tile = blockIdx.x; tile < ntiles; tile += gridDim.x) {
        const int row0 = tile * 32;
        { // load 32x256 hidden-state tile (contiguous 32KB = 2048 float4)
            const float4* src = (const float4*)(g_Hs + (size_t)row0 * HDIM);
            float4* dst = (float4*)sht;
            #pragma unroll
            for (int q = 0; q < 8; q++) dst[q * 256 + t] = src[q * 256 + t];
        }
        __syncthreads();

        // phase 1: z = tanh(h @ Whx + bhx)   (packed f32x2, 4 rows/thread)
        unsigned long long acc01[4], acc23[4];
        #pragma unroll
        for (int q = 0; q < 4; q++) { acc01[q] = 0ull; acc23[q] = 0ull; }
        #pragma unroll 2
        for (int i4 = 0; i4 < 256; i4 += 4) {
            float hq[4][4];
            #pragma unroll
            for (int q = 0; q < 4; q++)
                *(float4*)&hq[q][0] = *(const float4*)&sht[(rg * 4 + q) * 256 + i4];
            #pragma unroll
            for (int s = 0; s < 4; s++) {
                ulonglong2 w = *(const ulonglong2*)&sWhx[(i4 + s) * 128 + jj4];
                #pragma unroll
                for (int q = 0; q < 4; q++) {
                    unsigned long long hs = pk2(hq[q][s]);
                    acc01[q] = fma2(hs, w.x, acc01[q]);
                    acc23[q] = fma2(hs, w.y, acc23[q]);
                }
            }
        }
        float4 bz = *(const float4*)&sbhx[jj4];
        #pragma unroll
        for (int q = 0; q < 4; q++) {
            const int rw = rg * 4 + q;
            sz[rw * 128 + jj4 + 0] = tanhf(pk_lo(acc01[q]) + bz.x);
            sz[rw * 128 + jj4 + 1] = tanhf(pk_hi(acc01[q]) + bz.y);
            sz[rw * 128 + jj4 + 2] = tanhf(pk_lo(acc23[q]) + bz.z);
            sz[rw * 128 + jj4 + 3] = tanhf(pk_hi(acc23[q]) + bz.w);
        }
        __syncthreads();

        // phase 2: y = z @ Wout + bout   (2 rows/thread)
        float4 o[2];
        o[0] = make_float4(0.f, 0.f, 0.f, 0.f);
        o[1] = make_float4(0.f, 0.f, 0.f, 0.f);
        #pragma unroll 2
        for (int j4 = 0; j4 < 128; j4 += 4) {
            float zq[2][4];
            #pragma unroll
            for (int q2 = 0; q2 < 2; q2++)
                *(float4*)&zq[q2][0] = *(const float4*)&sz[(rr * 2 + q2) * 128 + j4];
            #pragma unroll
            for (int s = 0; s < 4; s++) {
                float4 w = *(const float4*)&sWout[(j4 + s) * 64 + oo4];
                #pragma unroll
                for (int q2 = 0; q2 < 2; q2++) {
                    o[q2].x = fmaf(zq[q2][s], w.x, o[q2].x);
                    o[q2].y = fmaf(zq[q2][s], w.y, o[q2].y);
                    o[q2].z = fmaf(zq[q2][s], w.z, o[q2].z);
                    o[q2].w = fmaf(zq[q2][s], w.w, o[q2].w);
                }
            }
        }
        float4 bo = *(const float4*)&sbout[oo4];
        #pragma unroll
        for (int q2 = 0; q2 < 2; q2++) {
            float4 ov;
            ov.x = o[q2].x + bo.x; ov.y = o[q2].y + bo.y;
            ov.z = o[q2].z + bo.z; ov.w = o[q2].w + bo.w;
            *((float4*)&y[(size_t)(row0 + rr * 2 + q2) * ODIM + oo4]) = ov;
        }
        __syncthreads();
    }
}

// ---------------------------------------------------------------------------
extern "C" void kernel_launch(void* const* d_in, const int* in_sizes, int n_in,
                              void* d_out, int out_size)
{
    const float* x      = (const float*)d_in[0];
    const float* Wx     = (const float*)d_in[1];
    const float* bx     = (const float*)d_in[2];
    const float* Wih    = (const float*)d_in[3];
    const float* bih    = (const float*)d_in[4];
    const float* Whh    = (const float*)d_in[5];
    const float* bhh    = (const float*)d_in[6];
    const float* Whx    = (const float*)d_in[7];
    const float* bhx    = (const float*)d_in[8];
    const float* Wout   = (const float*)d_in[9];
    const float* bout   = (const float*)d_in[10];
    const float* sigmas = (const float*)d_in[11];
    float* y = (float*)d_out;

    const size_t smA = (size_t)(64*128 + 128*260 + 128 + 256 + 32*64 + 32*128) * 4;
    const size_t smC = (size_t)(256*128 + 128*64 + 128 + 64 + 32*256 + 32*128) * 4;

    cudaFuncSetAttribute(kA, cudaFuncAttributeMaxDynamicSharedMemorySize, (int)smA);
    cudaFuncSetAttribute(kC, cudaFuncAttributeMaxDynamicSharedMemorySize, (int)smC);

    kA<<<148, 256, smA>>>(x, Wx, bx, Wih, bih, bhh);
    kB<<<64, 256>>>(Whh, sigmas);
    kC<<<148, 256, smC>>>(Whx, bhx, Wout, bout, y);
}